// round 4
// baseline (speedup 1.0000x reference)
#include <cuda_runtime.h>

#define CHN   4
#define HHT   128
#define WWD   128
#define TT    50
#define TP    52          // padded t-stride: mult of 4 (LDS.128) & conflict-free
#define SOP   51          // staging row stride: gcd(51,32)=1 -> conflict-free scalar
#define NBATCH 8
#define NPIX  (NBATCH*CHN*HHT*WWD)   // 524288
#define NELEM (NPIX*TT)              // 26214400

__device__ float g_bufA[NELEM];
__device__ float g_bufB[NELEM];

// packed fp32x2 FMA (2 independent fp32 FMAs per instruction; bit-exact)
__device__ __forceinline__ void fma2(unsigned long long& d,
                                     unsigned long long a, unsigned long long b) {
    asm("fma.rn.f32x2 %0, %1, %2, %0;" : "+l"(d) : "l"(a), "l"(b));
}
__device__ __forceinline__ float2 upk(unsigned long long v) {
    float2 f;
    f.x = __uint_as_float((unsigned)(v & 0xffffffffull));
    f.y = __uint_as_float((unsigned)(v >> 32));
    return f;
}

// ---------------------------------------------------------------------------
// Standalone alpha-PSP (layer 1 input). Warp-local smem transpose.
// ---------------------------------------------------------------------------
#define PW_PAD 53
#define PW_WARPS 8
#define PW_SMEM (PW_WARPS * 32 * PW_PAD * 4)

__global__ void __launch_bounds__(256, 4) psp_kernel(const float* __restrict__ in,
                                                     float* __restrict__ out,
                                                     float r, float coef) {
    extern __shared__ float sm[];
    const int lane = threadIdx.x & 31;
    const int wrp  = threadIdx.x >> 5;
    float* ws = sm + wrp * 32 * PW_PAD;
    const long base = (long)(blockIdx.x * (PW_WARPS * 32) + wrp * 32) * TT;
    const float* g = in + base;
#pragma unroll
    for (int w = 0; w < 32; ++w) {
        ws[w * PW_PAD + lane] = g[w * TT + lane];
        if (lane < TT - 32) ws[w * PW_PAD + 32 + lane] = g[w * TT + 32 + lane];
    }
    __syncwarp();
    float* row = ws + lane * PW_PAD;
    float s1 = 0.f, s2 = 0.f;
#pragma unroll
    for (int t = 0; t < TT; ++t) {
        float x = row[t];
        row[t] = coef * s2;
        s1 = fmaf(r, s1, x);
        s2 = fmaf(r, s2, r * s1);
    }
    __syncwarp();
    float* o = out + base;
#pragma unroll
    for (int w = 0; w < 32; ++w) {
        o[w * TT + lane] = ws[w * PW_PAD + lane];
        if (lane < TT - 32) o[w * TT + 32 + lane] = ws[w * PW_PAD + 32 + lane];
    }
}

// ---------------------------------------------------------------------------
// Fused conv(KxK, 4->4, pad K/2) + spike-dynamics epilogue.
// EPI=0: epilogue = spike + next-layer psp. EPI=1: spike only (binary out).
// Block = (32w, h, n), 416 thr = 13 warps. ci in passes of CIH channels.
// Thread (lane=w, wrp->t0=4*wrp) accumulates 4 co x 4 t via fma.rn.f32x2.
// SMEM s_in rows are NOT zero-initialized except OOB halo rows; junk in
// t-pad cols 50..51 only feeds accumulator halves that are discarded.
// ---------------------------------------------------------------------------
template <int K, int CIH, int EPI>
__global__ void __launch_bounds__(416, 2)
conv_fused_kernel(const float* __restrict__ in, const float* __restrict__ wts,
                  float* __restrict__ out,
                  float rR, float cR, float theta, float rP, float cP) {
    constexpr int PAD = K / 2;
    constexpr int WH  = 32 + 2 * PAD;
    constexpr int NT  = 416;
    constexpr int SIN = CIH * K * WH * TP;
    constexpr int NW  = CHN * CHN * K * K;

    extern __shared__ float sm[];
    float* s_in = sm;
    float* s_w  = sm + SIN;

    const int tid  = threadIdx.x;
    const int lane = tid & 31;
    const int wrp  = tid >> 5;
    const int w0   = blockIdx.x * 32;
    const int h    = blockIdx.y;
    const int n    = blockIdx.z;

    // weights OIHW -> smem [(ci,kh,kw)][co dup x2] (for broadcast LDS.128 pairs)
    if (tid < NW) {
        int co = tid / (CHN * K * K);
        int r  = tid % (CHN * K * K);
        float v = wts[tid];
        s_w[r * 8 + co * 2 + 0] = v;
        s_w[r * 8 + co * 2 + 1] = v;
    }

    const int t0 = wrp * 4;

    unsigned long long acc2[4][2];   // [co][(t0,t0+1)|(t0+2,t0+3)]
#pragma unroll
    for (int c = 0; c < 4; ++c) { acc2[c][0] = 0ull; acc2[c][1] = 0ull; }

#pragma unroll
    for (int cib = 0; cib < CHN; cib += CIH) {
        __syncthreads();   // previous pass compute done before overwrite
        // fill: copy valid rows, zero OOB halo rows (no full memset)
        for (int ci = 0; ci < CIH; ++ci) {
#pragma unroll
            for (int kh = 0; kh < K; ++kh) {
                const int hh = h + kh - PAD;
                const bool hok = (hh >= 0) && (hh < HHT);
                const float* src = in + (((long)(n * CHN + cib + ci) * HHT + hh) * WWD + (w0 - PAD)) * TT;
                float* dst = s_in + (ci * K + kh) * WH * TP;
                for (int row = wrp; row < WH; row += 13) {
                    const int wg = w0 - PAD + row;
                    const bool ok = hok && (wg >= 0) && (wg < WWD);
                    float v0 = 0.f, v1 = 0.f;
                    if (ok) {
                        v0 = src[row * TT + lane];
                        if (lane < TT - 32) v1 = src[row * TT + 32 + lane];
                    }
                    dst[row * TP + lane] = v0;
                    if (lane < TT - 32) dst[row * TP + 32 + lane] = v1;
                }
            }
        }
        __syncthreads();
        // inner loop: LDS.128 + FFMA2 only, fully unrolled
#pragma unroll
        for (int ci = 0; ci < CIH; ++ci) {
#pragma unroll
            for (int kh = 0; kh < K; ++kh) {
                const float* rowp = s_in + ((ci * K + kh) * WH + lane) * TP + t0;
                const float* wp   = s_w + ((cib + ci) * K + kh) * K * 8;
#pragma unroll
                for (int kw = 0; kw < K; ++kw) {
                    const ulonglong2 iv = *reinterpret_cast<const ulonglong2*>(rowp + kw * TP);
                    const ulonglong2 wa = *reinterpret_cast<const ulonglong2*>(wp + kw * 8);
                    const ulonglong2 wb = *reinterpret_cast<const ulonglong2*>(wp + kw * 8 + 4);
                    fma2(acc2[0][0], iv.x, wa.x);
                    fma2(acc2[0][1], iv.y, wa.x);
                    fma2(acc2[1][0], iv.x, wa.y);
                    fma2(acc2[1][1], iv.y, wa.y);
                    fma2(acc2[2][0], iv.x, wb.x);
                    fma2(acc2[2][1], iv.y, wb.x);
                    fma2(acc2[3][0], iv.x, wb.y);
                    fma2(acc2[3][1], iv.y, wb.y);
                }
            }
        }
    }
    __syncthreads();

    // stage conv results: s_out[co][w][t], row stride SOP (conflict-free)
    float* s_out = sm;   // overlay: 4*32*51 floats << SIN
#pragma unroll
    for (int co = 0; co < 4; ++co) {
        float* p = s_out + co * (32 * SOP) + lane * SOP + t0;
        float2 a = upk(acc2[co][0]);
        float2 b = upk(acc2[co][1]);
        p[0] = a.x;
        p[1] = a.y;
        if (t0 + 2 < TT) p[2] = b.x;
        if (t0 + 3 < TT) p[3] = b.y;
    }
    __syncthreads();

    // fused spike-dynamics epilogue: 128 pixels, conflict-free rows
    if (tid < 128) {
        const int co = tid >> 5;
        const int w  = tid & 31;
        float* row = s_out + co * (32 * SOP) + w * SOP;
        float sd1 = 0.f, sd2 = 0.f, sp1 = 0.f, sp2 = 0.f;
#pragma unroll
        for (int t = 0; t < TT; ++t) {
            float m = fmaf(cR, sd2, row[t]);
            float s = (m >= theta) ? 1.f : 0.f;
            sd1 = fmaf(rR, sd1, s);
            sd2 = fmaf(rR, sd2, rR * sd1);
            if (EPI == 0) {
                row[t] = cP * sp2;
                sp1 = fmaf(rP, sp1, s);
                sp2 = fmaf(rP, sp2, rP * sp1);
            } else {
                row[t] = s;
            }
        }
    }
    __syncthreads();

    // coalesced global store
    for (int e = tid; e < 4 * 32 * TT; e += NT) {
        int co  = e / (32 * TT);
        int rem = e - co * (32 * TT);    // = w*TT + t
        int w   = rem / TT;
        int t   = rem - w * TT;
        out[(((long)(n * CHN + co) * HHT + h) * WWD + w0) * TT + rem] =
            s_out[co * (32 * SOP) + w * SOP + t];
    }
}

// ---------------------------------------------------------------------------

extern "C" void kernel_launch(void* const* d_in, const int* in_sizes, int n_in,
                              void* d_out, int out_size) {
    const float* x  = (const float*)d_in[0];
    const float* w1 = (const float*)d_in[1];
    const float* w2 = (const float*)d_in[2];
    float* outp = (float*)d_out;

    float *bufA, *bufB;
    cudaGetSymbolAddress((void**)&bufA, g_bufA);
    cudaGetSymbolAddress((void**)&bufB, g_bufB);

    // conv5 CIH=2: 2*5*36*52*4 + 4*25*8*4 = 74880 + 3200 = 78080 B -> 2 blocks/SM
    // conv3 CIH=4: 4*3*34*52*4 + 4*9*8*4  = 84864 + 1152 = 86016 B -> 2 blocks/SM, 1 pass
    const int SMEM5 = 2 * 5 * 36 * TP * 4 + CHN * 25 * 8 * 4;
    const int SMEM3 = 4 * 3 * 34 * TP * 4 + CHN * 9 * 8 * 4;
    cudaFuncSetAttribute((const void*)conv_fused_kernel<5, 2, 0>,
                         cudaFuncAttributeMaxDynamicSharedMemorySize, SMEM5);
    cudaFuncSetAttribute((const void*)conv_fused_kernel<3, 4, 1>,
                         cudaFuncAttributeMaxDynamicSharedMemorySize, SMEM3);
    cudaFuncSetAttribute((const void*)psp_kernel,
                         cudaFuncAttributeMaxDynamicSharedMemorySize, PW_SMEM);

    const float r1  = (float)0.36787944117144233;   // exp(-1/tau1)
    const float cP1 = (float)2.718281828459045;     // e/tau1
    const float rR1 = (float)0.36787944117144233;   // exp(-1/tauRef1)
    const float cR1 = (float)(-54.365636569180902); // -scaleRef*theta1*e/tauRef1
    const float th1 = 20.0f;
    const float r2  = (float)0.6065306597126334;    // exp(-1/tau2)
    const float cP2 = (float)1.3591409142295225;    // e/tau2
    const float rR2 = (float)0.6065306597126334;    // exp(-1/tauRef2)
    const float cR2 = (float)(-54.365636569180902); // -scaleRef*theta2*e/tauRef2
    const float th2 = 40.0f;

    const int PGRID = NPIX / (PW_WARPS * 32);   // 2048
    dim3 cgrid(WWD / 32, HHT, NBATCH);          // (4,128,8)

    psp_kernel<<<PGRID, 256, PW_SMEM>>>(x, bufA, r1, cP1);
    conv_fused_kernel<5, 2, 0><<<cgrid, 416, SMEM5>>>(bufA, w1, bufB,
                                                      rR1, cR1, th1, r2, cP2);
    conv_fused_kernel<3, 4, 1><<<cgrid, 416, SMEM3>>>(bufB, w2, outp,
                                                      rR2, cR2, th2, 0.f, 0.f);
}

// round 5
// speedup vs baseline: 1.1749x; 1.1749x over previous
#include <cuda_runtime.h>

#define CHN   4
#define HHT   128
#define WWD   128
#define TT    50
#define TPD   58          // smem row stride (floats): TPD%8==2 -> conflict-free LDS.64
#define SOP   51          // staging row stride: gcd(51,32)=1 -> conflict-free recurrence
#define NBATCH 8
#define NPIX  (NBATCH*CHN*HHT*WWD)
#define NELEM (NPIX*TT)

__device__ float g_bufA[NELEM];
__device__ float g_bufB[NELEM];

typedef unsigned long long u64;

__device__ __forceinline__ void fma2(u64& d, u64 a, u64 b) {
    asm("fma.rn.f32x2 %0, %1, %2, %0;" : "+l"(d) : "l"(a), "l"(b));
}
__device__ __forceinline__ float2 upk(u64 v) {
    float2 f;
    f.x = __uint_as_float((unsigned)(v & 0xffffffffull));
    f.y = __uint_as_float((unsigned)(v >> 32));
    return f;
}

// ---------------------------------------------------------------------------
// Standalone alpha-PSP (layer 1). Warp-local smem transpose. (unchanged, 39us)
// ---------------------------------------------------------------------------
#define PW_PAD 53
#define PW_WARPS 8
#define PW_SMEM (PW_WARPS * 32 * PW_PAD * 4)

__global__ void __launch_bounds__(256, 4) psp_kernel(const float* __restrict__ in,
                                                     float* __restrict__ out,
                                                     float r, float coef) {
    extern __shared__ float sm[];
    const int lane = threadIdx.x & 31;
    const int wrp  = threadIdx.x >> 5;
    float* ws = sm + wrp * 32 * PW_PAD;
    const long base = (long)(blockIdx.x * (PW_WARPS * 32) + wrp * 32) * TT;
    const float* g = in + base;
#pragma unroll
    for (int w = 0; w < 32; ++w) {
        ws[w * PW_PAD + lane] = g[w * TT + lane];
        if (lane < TT - 32) ws[w * PW_PAD + 32 + lane] = g[w * TT + 32 + lane];
    }
    __syncwarp();
    float* row = ws + lane * PW_PAD;
    float s1 = 0.f, s2 = 0.f;
#pragma unroll
    for (int t = 0; t < TT; ++t) {
        float x = row[t];
        row[t] = coef * s2;
        s1 = fmaf(r, s1, x);
        s2 = fmaf(r, s2, r * s1);
    }
    __syncwarp();
    float* o = out + base;
#pragma unroll
    for (int w = 0; w < 32; ++w) {
        o[w * TT + lane] = ws[w * PW_PAD + lane];
        if (lane < TT - 32) o[w * TT + 32 + lane] = ws[w * PW_PAD + 32 + lane];
    }
}

// ---------------------------------------------------------------------------
// Fused conv(KxK, 4->4, pad K/2) + spike epilogue, w-register-blocked.
// Block = (32w, 2h, n): 448 thr = 14 warps (7 per h sub-row).
// Thread (hs, wip, lane): wg = lane>>2 (w block of 4), tp_lo = lane&3,
// tp = wip*4+tp_lo (t pair, t0=2*tp, valid tp<25), computes 4w x 4co x 2t.
// Per (ci,kh): load K+3 input t-pairs (LDS.64, conflict-free), slide kw in
// registers; weights via broadcast LDS.128 (dup pairs). FMA-bound inner loop.
// EPI=0: spike + next psp. EPI=1: spike only.
// ---------------------------------------------------------------------------
template <int K, int CIH, int EPI>
__global__ void __launch_bounds__(448, 2)
conv_fused_kernel(const float* __restrict__ in, const float* __restrict__ wts,
                  float* __restrict__ out,
                  float rR, float cR, float theta, float rP, float cP) {
    constexpr int PAD   = K / 2;
    constexpr int WH    = 32 + 2 * PAD;
    constexpr int HROWS = K + 1;          // input h rows for 2 output rows
    constexpr int NT    = 448;
    constexpr int NWARP = 14;
    constexpr int SIN   = CIH * HROWS * WH * TPD;
    constexpr int NW    = CHN * CHN * K * K;
    constexpr int NV    = 4 + K - 1;      // register window width

    extern __shared__ float sm[];
    float* s_in = sm;
    float* s_w  = sm + SIN;

    const int tid   = threadIdx.x;
    const int lane  = tid & 31;
    const int wrp   = tid >> 5;
    const int hs    = (wrp >= 7) ? 1 : 0;
    const int wip   = wrp - 7 * hs;
    const int tp_lo = lane & 3;
    const int wg    = lane >> 2;
    const int tp    = wip * 4 + tp_lo;    // 0..27, valid < 25
    const int t0    = tp * 2;

    const int w0 = blockIdx.x * 32;
    const int h0 = blockIdx.y * 2;
    const int n  = blockIdx.z;

    // weights OIHW -> smem [(ci,kh,kw)][co dup x2]
    if (tid < NW) {
        int co = tid / (CHN * K * K);
        int r  = tid % (CHN * K * K);
        float v = wts[tid];
        s_w[r * 8 + co * 2 + 0] = v;
        s_w[r * 8 + co * 2 + 1] = v;
    }

    u64 acc[4][4];   // [i=w offset][co], each = (t0, t0+1)
#pragma unroll
    for (int i = 0; i < 4; ++i)
#pragma unroll
        for (int c = 0; c < 4; ++c) acc[i][c] = 0ull;

#pragma unroll
    for (int cib = 0; cib < CHN; cib += CIH) {
        if (cib) __syncthreads();
        // fill: row (ci,hr,wr) -> flat rowi; copy t0..49, zero OOB rows
        for (int rowi = wrp; rowi < CIH * HROWS * WH; rowi += NWARP) {
            int ci = rowi / (HROWS * WH);
            int rm = rowi - ci * (HROWS * WH);
            int hr = rm / WH;
            int wr = rm - hr * WH;
            int hh = h0 - PAD + hr;
            int wgl = w0 - PAD + wr;
            bool ok = (hh >= 0) && (hh < HHT) && (wgl >= 0) && (wgl < WWD);
            float v0 = 0.f, v1 = 0.f;
            if (ok) {
                const float* src = in + (((long)(n * CHN + cib + ci) * HHT + hh) * WWD + wgl) * TT;
                v0 = src[lane];
                if (lane < TT - 32) v1 = src[32 + lane];
            }
            float* dst = s_in + rowi * TPD;
            dst[lane] = v0;
            if (lane < TT - 32) dst[32 + lane] = v1;
        }
        __syncthreads();
        // compute: register-blocked over w, slide kw in registers
#pragma unroll
        for (int ci = 0; ci < CIH; ++ci) {
#pragma unroll
            for (int kh = 0; kh < K; ++kh) {
                const float* vbase = s_in + (((ci * HROWS) + (hs + kh)) * WH + wg * 4) * TPD + t0;
                u64 v[NV];
#pragma unroll
                for (int j = 0; j < NV; ++j)
                    v[j] = *reinterpret_cast<const u64*>(vbase + j * TPD);
                const float* wp = s_w + ((cib + ci) * K + kh) * K * 8;
#pragma unroll
                for (int kw = 0; kw < K; ++kw) {
                    const ulonglong2 wa = *reinterpret_cast<const ulonglong2*>(wp + kw * 8);
                    const ulonglong2 wb = *reinterpret_cast<const ulonglong2*>(wp + kw * 8 + 4);
#pragma unroll
                    for (int i = 0; i < 4; ++i) {
                        fma2(acc[i][0], v[i + kw], wa.x);
                        fma2(acc[i][1], v[i + kw], wa.y);
                        fma2(acc[i][2], v[i + kw], wb.x);
                        fma2(acc[i][3], v[i + kw], wb.y);
                    }
                }
            }
        }
    }
    __syncthreads();

    // stage: s_out[hs][co][w][SOP]
    float* s_out = sm;   // overlay (compute finished): 2*4*32*51 = 52.2KB < SIN
    if (tp < 25) {
#pragma unroll
        for (int co = 0; co < 4; ++co)
#pragma unroll
            for (int i = 0; i < 4; ++i) {
                float2 a = upk(acc[i][co]);
                float* p = s_out + ((hs * 4 + co) * 32 + wg * 4 + i) * SOP + t0;
                p[0] = a.x;
                p[1] = a.y;
            }
    }
    __syncthreads();

    // fused spike-dynamics epilogue: 256 pixels (2hs x 4co x 32w)
    if (tid < 256) {
        const int hs2 = tid >> 7;
        const int co  = (tid >> 5) & 3;
        const int w   = tid & 31;
        float* row = s_out + ((hs2 * 4 + co) * 32 + w) * SOP;
        float sd1 = 0.f, sd2 = 0.f, sp1 = 0.f, sp2 = 0.f;
#pragma unroll
        for (int t = 0; t < TT; ++t) {
            float m = fmaf(cR, sd2, row[t]);
            float s = (m >= theta) ? 1.f : 0.f;
            sd1 = fmaf(rR, sd1, s);
            sd2 = fmaf(rR, sd2, rR * sd1);
            if (EPI == 0) {
                row[t] = cP * sp2;
                sp1 = fmaf(rP, sp1, s);
                sp2 = fmaf(rP, sp2, rP * sp1);
            } else {
                row[t] = s;
            }
        }
    }
    __syncthreads();

    // coalesced global store: 2hs x 4co x 32w x 50t
    for (int e = tid; e < 2 * 4 * 32 * TT; e += NT) {
        int hs2 = (e >= 4 * 32 * TT) ? 1 : 0;
        int r1  = e - hs2 * (4 * 32 * TT);
        int co  = r1 / (32 * TT);
        int r2  = r1 - co * (32 * TT);
        int w   = r2 / TT;
        int t   = r2 - w * TT;
        out[(((long)(n * CHN + co) * HHT + (h0 + hs2)) * WWD + w0 + w) * TT + t] =
            s_out[((hs2 * 4 + co) * 32 + w) * SOP + t];
    }
}

// ---------------------------------------------------------------------------

extern "C" void kernel_launch(void* const* d_in, const int* in_sizes, int n_in,
                              void* d_out, int out_size) {
    const float* x  = (const float*)d_in[0];
    const float* w1 = (const float*)d_in[1];
    const float* w2 = (const float*)d_in[2];
    float* outp = (float*)d_out;

    float *bufA, *bufB;
    cudaGetSymbolAddress((void**)&bufA, g_bufA);
    cudaGetSymbolAddress((void**)&bufB, g_bufB);

    // conv5 CIH=2: s_in 2*6*36*58*4 = 100224 + w 4*25*8*4 = 3200 -> 103424 B, 2 blk/SM
    // conv3 CIH=2: s_in 2*4*34*58*4 =  63104 + w 4*9*8*4  = 1152 ->  64256 B, 2 blk/SM
    const int SMEM5 = 2 * 6 * 36 * TPD * 4 + CHN * CHN * 25 * 8;
    const int SMEM3 = 2 * 4 * 34 * TPD * 4 + CHN * CHN * 9 * 8;
    cudaFuncSetAttribute((const void*)conv_fused_kernel<5, 2, 0>,
                         cudaFuncAttributeMaxDynamicSharedMemorySize, SMEM5);
    cudaFuncSetAttribute((const void*)conv_fused_kernel<3, 2, 1>,
                         cudaFuncAttributeMaxDynamicSharedMemorySize, SMEM3);
    cudaFuncSetAttribute((const void*)psp_kernel,
                         cudaFuncAttributeMaxDynamicSharedMemorySize, PW_SMEM);

    const float r1  = (float)0.36787944117144233;   // exp(-1/tau1)
    const float cP1 = (float)2.718281828459045;     // e/tau1
    const float rR1 = (float)0.36787944117144233;   // exp(-1/tauRef1)
    const float cR1 = (float)(-54.365636569180902); // -scaleRef*theta1*e/tauRef1
    const float th1 = 20.0f;
    const float r2  = (float)0.6065306597126334;    // exp(-1/tau2)
    const float cP2 = (float)1.3591409142295225;    // e/tau2
    const float rR2 = (float)0.6065306597126334;    // exp(-1/tauRef2)
    const float cR2 = (float)(-54.365636569180902); // -scaleRef*theta2*e/tauRef2
    const float th2 = 40.0f;

    const int PGRID = NPIX / (PW_WARPS * 32);   // 2048
    dim3 cgrid(WWD / 32, HHT / 2, NBATCH);      // (4,64,8) = 2048 blocks

    psp_kernel<<<PGRID, 256, PW_SMEM>>>(x, bufA, r1, cP1);
    conv_fused_kernel<5, 2, 0><<<cgrid, 448, SMEM5>>>(bufA, w1, bufB,
                                                      rR1, cR1, th1, r2, cP2);
    conv_fused_kernel<3, 2, 1><<<cgrid, 448, SMEM3>>>(bufB, w2, outp,
                                                      rR2, cR2, th2, 0.f, 0.f);
}

// round 6
// speedup vs baseline: 1.4620x; 1.2444x over previous
#include <cuda_runtime.h>

#define CHN   4
#define HHT   128
#define WWD   128
#define TT    50
#define TP    52          // padded t-stride: mult of 4 (LDS.128), conflict-free
#define SOP   51          // staging row stride: gcd(51,32)=1 -> conflict-free
#define NBATCH 8
#define NPIX  (NBATCH*CHN*HHT*WWD)
#define NELEM (NPIX*TT)

__device__ float g_bufA[NELEM];
__device__ float g_bufB[NELEM];

typedef unsigned long long u64;

// Packed duplicated weights live in CONSTANT memory (separate port from the
// L1/smem crossbar -- this is the point of this round).
// c_w5d[tap*2+0] = (w0,w0,w1,w1), [tap*2+1] = (w2,w2,w3,w3), tap=(ci*5+kh)*5+kw
__constant__ ulonglong2 c_w5d[200];
__constant__ ulonglong2 c_w3d[72];
__device__ float4 g_wpack[272];   // staging for memcpy-to-symbol

template <int K>
__device__ __forceinline__ ulonglong2 cwload(int i);
template <>
__device__ __forceinline__ ulonglong2 cwload<5>(int i) { return c_w5d[i]; }
template <>
__device__ __forceinline__ ulonglong2 cwload<3>(int i) { return c_w3d[i]; }

__device__ __forceinline__ void fma2(u64& d, u64 a, u64 b) {
    asm("fma.rn.f32x2 %0, %1, %2, %0;" : "+l"(d) : "l"(a), "l"(b));
}
__device__ __forceinline__ float2 upk(u64 v) {
    float2 f;
    f.x = __uint_as_float((unsigned)(v & 0xffffffffull));
    f.y = __uint_as_float((unsigned)(v >> 32));
    return f;
}

// Repack OIHW weights -> duplicated-pair float4 staging (then D2D to constant).
__global__ void repack_kernel(const float* __restrict__ w1,
                              const float* __restrict__ w2) {
    int tid = threadIdx.x;
    if (tid < 100) {   // conv5: tap flat = ci*25+kh*5+kw == within-co OIHW index
        float a = w1[0 * 100 + tid], b = w1[1 * 100 + tid];
        float c = w1[2 * 100 + tid], d = w1[3 * 100 + tid];
        g_wpack[tid * 2 + 0] = make_float4(a, a, b, b);
        g_wpack[tid * 2 + 1] = make_float4(c, c, d, d);
    }
    if (tid >= 128 && tid < 164) {   // conv3: 36 taps
        int t = tid - 128;
        float a = w2[0 * 36 + t], b = w2[1 * 36 + t];
        float c = w2[2 * 36 + t], d = w2[3 * 36 + t];
        g_wpack[200 + t * 2 + 0] = make_float4(a, a, b, b);
        g_wpack[200 + t * 2 + 1] = make_float4(c, c, d, d);
    }
}

// ---------------------------------------------------------------------------
// Standalone alpha-PSP (layer 1). Warp-local smem transpose. (39us, near-roof)
// ---------------------------------------------------------------------------
#define PW_PAD 53
#define PW_WARPS 8
#define PW_SMEM (PW_WARPS * 32 * PW_PAD * 4)

__global__ void __launch_bounds__(256, 4) psp_kernel(const float* __restrict__ in,
                                                     float* __restrict__ out,
                                                     float r, float coef) {
    extern __shared__ float sm[];
    const int lane = threadIdx.x & 31;
    const int wrp  = threadIdx.x >> 5;
    float* ws = sm + wrp * 32 * PW_PAD;
    const long base = (long)(blockIdx.x * (PW_WARPS * 32) + wrp * 32) * TT;
    const float* g = in + base;
#pragma unroll
    for (int w = 0; w < 32; ++w) {
        ws[w * PW_PAD + lane] = g[w * TT + lane];
        if (lane < TT - 32) ws[w * PW_PAD + 32 + lane] = g[w * TT + 32 + lane];
    }
    __syncwarp();
    float* row = ws + lane * PW_PAD;
    float s1 = 0.f, s2 = 0.f;
#pragma unroll
    for (int t = 0; t < TT; ++t) {
        float x = row[t];
        row[t] = coef * s2;
        s1 = fmaf(r, s1, x);
        s2 = fmaf(r, s2, r * s1);
    }
    __syncwarp();
    float* o = out + base;
#pragma unroll
    for (int w = 0; w < 32; ++w) {
        o[w * TT + lane] = ws[w * PW_PAD + lane];
        if (lane < TT - 32) o[w * TT + 32 + lane] = ws[w * PW_PAD + 32 + lane];
    }
}

// ---------------------------------------------------------------------------
// Fused conv(KxK, 4->4, pad K/2) + spike epilogue. R3 structure, but weights
// come from CONSTANT memory (no crossbar traffic); smem holds input only.
// Block (32w, h, n), 416 thr = 13 warps, thread = (w=lane, t-quad t0=4*wrp).
// Per tap: 1 LDS.128 input + 2 LDC.128 weights + 8 FFMA2.
// ---------------------------------------------------------------------------
template <int K, int CIH, int EPI>
__global__ void __launch_bounds__(416, 3)
conv_fused_kernel(const float* __restrict__ in, float* __restrict__ out,
                  float rR, float cR, float theta, float rP, float cP) {
    constexpr int PAD = K / 2;
    constexpr int WH  = 32 + 2 * PAD;
    constexpr int NT  = 416;
    constexpr int SIN = CIH * K * WH * TP;

    extern __shared__ float sm[];
    float* s_in = sm;

    const int tid  = threadIdx.x;
    const int lane = tid & 31;
    const int wrp  = tid >> 5;
    const int w0   = blockIdx.x * 32;
    const int h    = blockIdx.y;
    const int n    = blockIdx.z;
    const int t0   = wrp * 4;

    u64 acc[4][2];   // [co][(t0,t0+1)|(t0+2,t0+3)]
#pragma unroll
    for (int c = 0; c < 4; ++c) { acc[c][0] = 0ull; acc[c][1] = 0ull; }

#pragma unroll
    for (int cib = 0; cib < CHN; cib += CIH) {
        if (cib) __syncthreads();
        // fill: bounds-checked copy, zero for OOB rows; t-pad cols left as-is
        // (they only feed acc halves discarded by the store guards)
        for (int rowi = wrp; rowi < CIH * K * WH; rowi += 13) {
            int ci = rowi / (K * WH);
            int rm = rowi - ci * (K * WH);
            int kh = rm / WH;
            int wr = rm - kh * WH;
            int hh = h + kh - PAD;
            int wg = w0 - PAD + wr;
            bool ok = (hh >= 0) && (hh < HHT) && (wg >= 0) && (wg < WWD);
            float v0 = 0.f, v1 = 0.f;
            if (ok) {
                const float* src = in + (((long)(n * CHN + cib + ci) * HHT + hh) * WWD + wg) * TT;
                v0 = src[lane];
                if (lane < TT - 32) v1 = src[32 + lane];
            }
            float* dst = s_in + rowi * TP;
            dst[lane] = v0;
            if (lane < TT - 32) dst[32 + lane] = v1;
        }
        __syncthreads();
        // compute: input LDS.128 + constant-port weights + FFMA2
#pragma unroll
        for (int ci = 0; ci < CIH; ++ci) {
#pragma unroll
            for (int kh = 0; kh < K; ++kh) {
                const float* rowp = s_in + ((ci * K + kh) * WH + lane) * TP + t0;
#pragma unroll
                for (int kw = 0; kw < K; ++kw) {
                    const int tap = ((cib + ci) * K + kh) * K + kw;
                    const ulonglong2 iv = *reinterpret_cast<const ulonglong2*>(rowp + kw * TP);
                    const ulonglong2 wa = cwload<K>(tap * 2);
                    const ulonglong2 wb = cwload<K>(tap * 2 + 1);
                    fma2(acc[0][0], iv.x, wa.x);
                    fma2(acc[0][1], iv.y, wa.x);
                    fma2(acc[1][0], iv.x, wa.y);
                    fma2(acc[1][1], iv.y, wa.y);
                    fma2(acc[2][0], iv.x, wb.x);
                    fma2(acc[2][1], iv.y, wb.x);
                    fma2(acc[3][0], iv.x, wb.y);
                    fma2(acc[3][1], iv.y, wb.y);
                }
            }
        }
    }
    __syncthreads();

    // stage conv results: s_out[co][w][SOP] (conflict-free recurrence rows)
    float* s_out = sm;   // overlay: 4*32*51 floats < SIN
#pragma unroll
    for (int co = 0; co < 4; ++co) {
        float* p = s_out + co * (32 * SOP) + lane * SOP + t0;
        float2 a = upk(acc[co][0]);
        float2 b = upk(acc[co][1]);
        p[0] = a.x;
        p[1] = a.y;
        if (t0 + 2 < TT) p[2] = b.x;
        if (t0 + 3 < TT) p[3] = b.y;
    }
    __syncthreads();

    // fused spike-dynamics epilogue: 128 pixels (4co x 32w)
    if (tid < 128) {
        const int co = tid >> 5;
        const int w  = tid & 31;
        float* row = s_out + co * (32 * SOP) + w * SOP;
        float sd1 = 0.f, sd2 = 0.f, sp1 = 0.f, sp2 = 0.f;
#pragma unroll
        for (int t = 0; t < TT; ++t) {
            float m = fmaf(cR, sd2, row[t]);
            float s = (m >= theta) ? 1.f : 0.f;
            sd1 = fmaf(rR, sd1, s);
            sd2 = fmaf(rR, sd2, rR * sd1);
            if (EPI == 0) {
                row[t] = cP * sp2;
                sp1 = fmaf(rP, sp1, s);
                sp2 = fmaf(rP, sp2, rP * sp1);
            } else {
                row[t] = s;
            }
        }
    }
    __syncthreads();

    // coalesced global store
    for (int e = tid; e < 4 * 32 * TT; e += NT) {
        int co  = e / (32 * TT);
        int rem = e - co * (32 * TT);   // = w*TT + t
        int w   = rem / TT;
        int t   = rem - w * TT;
        out[(((long)(n * CHN + co) * HHT + h) * WWD + w0) * TT + rem] =
            s_out[co * (32 * SOP) + w * SOP + t];
    }
}

// ---------------------------------------------------------------------------

extern "C" void kernel_launch(void* const* d_in, const int* in_sizes, int n_in,
                              void* d_out, int out_size) {
    const float* x  = (const float*)d_in[0];
    const float* w1 = (const float*)d_in[1];
    const float* w2 = (const float*)d_in[2];
    float* outp = (float*)d_out;

    float *bufA, *bufB;
    cudaGetSymbolAddress((void**)&bufA, g_bufA);
    cudaGetSymbolAddress((void**)&bufB, g_bufB);
    float4* wpack;
    cudaGetSymbolAddress((void**)&wpack, g_wpack);

    // conv5 CIH=1: 1*5*36*52*4 = 37440 B -> 3 blocks/SM (112 KB, 39 warps)
    // conv3 CIH=2: 2*3*34*52*4 = 42432 B -> 3 blocks/SM (127 KB, 39 warps)
    const int SMEM5 = 1 * 5 * 36 * TP * 4;
    const int SMEM3 = 2 * 3 * 34 * TP * 4;
    cudaFuncSetAttribute((const void*)conv_fused_kernel<5, 1, 0>,
                         cudaFuncAttributeMaxDynamicSharedMemorySize, SMEM5);
    cudaFuncSetAttribute((const void*)conv_fused_kernel<3, 2, 1>,
                         cudaFuncAttributeMaxDynamicSharedMemorySize, SMEM3);
    cudaFuncSetAttribute((const void*)psp_kernel,
                         cudaFuncAttributeMaxDynamicSharedMemorySize, PW_SMEM);

    const float r1  = (float)0.36787944117144233;   // exp(-1/tau1)
    const float cP1 = (float)2.718281828459045;     // e/tau1
    const float rR1 = (float)0.36787944117144233;   // exp(-1/tauRef1)
    const float cR1 = (float)(-54.365636569180902); // -scaleRef*theta1*e/tauRef1
    const float th1 = 20.0f;
    const float r2  = (float)0.6065306597126334;    // exp(-1/tau2)
    const float cP2 = (float)1.3591409142295225;    // e/tau2
    const float rR2 = (float)0.6065306597126334;    // exp(-1/tauRef2)
    const float cR2 = (float)(-54.365636569180902); // -scaleRef*theta2*e/tauRef2
    const float th2 = 40.0f;

    const int PGRID = NPIX / (PW_WARPS * 32);   // 2048
    dim3 cgrid(WWD / 32, HHT, NBATCH);          // (4,128,8)

    // weights -> constant (graph-capturable: kernel + async D2D memcpy nodes)
    repack_kernel<<<1, 256>>>(w1, w2);
    cudaMemcpyToSymbolAsync(c_w5d, wpack, 200 * sizeof(float4), 0,
                            cudaMemcpyDeviceToDevice, 0);
    cudaMemcpyToSymbolAsync(c_w3d, wpack + 200, 72 * sizeof(float4), 0,
                            cudaMemcpyDeviceToDevice, 0);

    psp_kernel<<<PGRID, 256, PW_SMEM>>>(x, bufA, r1, cP1);
    conv_fused_kernel<5, 1, 0><<<cgrid, 416, SMEM5>>>(bufA, bufB,
                                                      rR1, cR1, th1, r2, cP2);
    conv_fused_kernel<3, 2, 1><<<cgrid, 416, SMEM3>>>(bufB, outp,
                                                      rR2, cR2, th2, 0.f, 0.f);
}

// round 7
// speedup vs baseline: 1.6426x; 1.1235x over previous
#include <cuda_runtime.h>

#define CHN   4
#define HHT   128
#define WWD   128
#define TT    50
#define TP    52          // padded t-stride: mult of 4 (LDS.128), conflict-free
#define SOP   51          // staging row stride: gcd(51,32)=1 -> conflict-free
#define NBATCH 8
#define NPIX  (NBATCH*CHN*HHT*WWD)
#define NELEM (NPIX*TT)

__device__ float g_bufA[NELEM];
__device__ float g_bufB[NELEM];

typedef unsigned long long u64;

// Weights in CONSTANT memory (separate port from the L1/smem crossbar).
// c_w5[tap] = (w_co0, w_co1, w_co2, w_co3), tap = (ci*5+kh)*5+kw
__constant__ float4 c_w5[100];
__constant__ float4 c_w3[36];
__device__ float4 g_wpack[136];   // staging for memcpy-to-symbol

template <int K>
__device__ __forceinline__ float4 cwload(int i);
template <>
__device__ __forceinline__ float4 cwload<5>(int i) { return c_w5[i]; }
template <>
__device__ __forceinline__ float4 cwload<3>(int i) { return c_w3[i]; }

__device__ __forceinline__ void fma2(u64& d, u64 a, u64 b) {
    asm("fma.rn.f32x2 %0, %1, %2, %0;" : "+l"(d) : "l"(a), "l"(b));
}
__device__ __forceinline__ u64 dup2(float w) {
    u64 d;
    asm("mov.b64 %0, {%1, %1};" : "=l"(d) : "f"(w));
    return d;
}
__device__ __forceinline__ float2 upk(u64 v) {
    float2 f;
    f.x = __uint_as_float((unsigned)(v & 0xffffffffull));
    f.y = __uint_as_float((unsigned)(v >> 32));
    return f;
}

// Repack OIHW -> per-tap float4 (co-vector) staging, then D2D to constant.
__global__ void repack_kernel(const float* __restrict__ w1,
                              const float* __restrict__ w2) {
    int tid = threadIdx.x;
    if (tid < 100)
        g_wpack[tid] = make_float4(w1[tid], w1[100 + tid], w1[200 + tid], w1[300 + tid]);
    if (tid >= 128 && tid < 164) {
        int t = tid - 128;
        g_wpack[100 + t] = make_float4(w2[t], w2[36 + t], w2[72 + t], w2[108 + t]);
    }
}

// ---------------------------------------------------------------------------
// Standalone alpha-PSP (layer 1). Warp-local smem transpose. (39us, near-roof)
// ---------------------------------------------------------------------------
#define PW_PAD 53
#define PW_WARPS 8
#define PW_SMEM (PW_WARPS * 32 * PW_PAD * 4)

__global__ void __launch_bounds__(256, 4) psp_kernel(const float* __restrict__ in,
                                                     float* __restrict__ out,
                                                     float r, float coef) {
    extern __shared__ float sm[];
    const int lane = threadIdx.x & 31;
    const int wrp  = threadIdx.x >> 5;
    float* ws = sm + wrp * 32 * PW_PAD;
    const long base = (long)(blockIdx.x * (PW_WARPS * 32) + wrp * 32) * TT;
    const float* g = in + base;
#pragma unroll
    for (int w = 0; w < 32; ++w) {
        ws[w * PW_PAD + lane] = g[w * TT + lane];
        if (lane < TT - 32) ws[w * PW_PAD + 32 + lane] = g[w * TT + 32 + lane];
    }
    __syncwarp();
    float* row = ws + lane * PW_PAD;
    float s1 = 0.f, s2 = 0.f;
#pragma unroll
    for (int t = 0; t < TT; ++t) {
        float x = row[t];
        row[t] = coef * s2;
        s1 = fmaf(r, s1, x);
        s2 = fmaf(r, s2, r * s1);
    }
    __syncwarp();
    float* o = out + base;
#pragma unroll
    for (int w = 0; w < 32; ++w) {
        o[w * TT + lane] = ws[w * PW_PAD + lane];
        if (lane < TT - 32) o[w * TT + 32 + lane] = ws[w * PW_PAD + 32 + lane];
    }
}

// ---------------------------------------------------------------------------
// Fused conv(KxK, 4->4, pad K/2) + spike epilogue.
// Block (32w, h, n), 416 thr = 13 warps, thread = (w=lane, t-quad t0=4*wrp).
// Per tap: 1 LDS.128 input + 1 LDC.128 weights + 4 mov.b64 packs + 8 FFMA2.
// Fill & store are fully structured (no div/mod) -> minimal ALU traffic.
// ---------------------------------------------------------------------------
template <int K, int CIH, int EPI>
__global__ void __launch_bounds__(416, 3)
conv_fused_kernel(const float* __restrict__ in, float* __restrict__ out,
                  float rR, float cR, float theta, float rP, float cP) {
    constexpr int PAD = K / 2;
    constexpr int WH  = 32 + 2 * PAD;
    constexpr int SIN = CIH * K * WH * TP;

    extern __shared__ float sm[];
    float* s_in = sm;

    const int tid  = threadIdx.x;
    const int lane = tid & 31;
    const int wrp  = tid >> 5;
    const int w0   = blockIdx.x * 32;
    const int h    = blockIdx.y;
    const int n    = blockIdx.z;
    const int t0   = wrp * 4;

    u64 acc[4][2];   // [co][(t0,t0+1)|(t0+2,t0+3)]
#pragma unroll
    for (int c = 0; c < 4; ++c) { acc[c][0] = 0ull; acc[c][1] = 0ull; }

#pragma unroll
    for (int cib = 0; cib < CHN; cib += CIH) {
        if (cib) __syncthreads();
        // structured fill: unrolled (ci,kh), row += 13 -> pure address adds
        for (int ci = 0; ci < CIH; ++ci) {
#pragma unroll
            for (int kh = 0; kh < K; ++kh) {
                const int hh  = h + kh - PAD;
                const bool hok = (hh >= 0) && (hh < HHT);
                const float* src = in + (((long)(n * CHN + cib + ci) * HHT + hh) * WWD + (w0 - PAD)) * TT;
                float* dst = s_in + (ci * K + kh) * WH * TP;
                for (int row = wrp; row < WH; row += 13) {
                    const int wg = w0 - PAD + row;
                    const bool ok = hok && (wg >= 0) && (wg < WWD);
                    float v0 = 0.f, v1 = 0.f;
                    if (ok) {
                        v0 = src[row * TT + lane];
                        if (lane < TT - 32) v1 = src[row * TT + 32 + lane];
                    }
                    dst[row * TP + lane] = v0;
                    if (lane < TT - 32) dst[row * TP + 32 + lane] = v1;
                }
            }
        }
        __syncthreads();
        // compute: LDS.128 input + LDC.128 weights + packs + FFMA2
#pragma unroll
        for (int ci = 0; ci < CIH; ++ci) {
#pragma unroll
            for (int kh = 0; kh < K; ++kh) {
                const float* rowp = s_in + ((ci * K + kh) * WH + lane) * TP + t0;
#pragma unroll
                for (int kw = 0; kw < K; ++kw) {
                    const int tap = ((cib + ci) * K + kh) * K + kw;
                    const ulonglong2 iv = *reinterpret_cast<const ulonglong2*>(rowp + kw * TP);
                    const float4 wv = cwload<K>(tap);
                    const u64 w0d = dup2(wv.x);
                    const u64 w1d = dup2(wv.y);
                    const u64 w2d = dup2(wv.z);
                    const u64 w3d = dup2(wv.w);
                    fma2(acc[0][0], iv.x, w0d);
                    fma2(acc[0][1], iv.y, w0d);
                    fma2(acc[1][0], iv.x, w1d);
                    fma2(acc[1][1], iv.y, w1d);
                    fma2(acc[2][0], iv.x, w2d);
                    fma2(acc[2][1], iv.y, w2d);
                    fma2(acc[3][0], iv.x, w3d);
                    fma2(acc[3][1], iv.y, w3d);
                }
            }
        }
    }
    __syncthreads();

    // stage conv results: s_out[co][w][SOP]
    float* s_out = sm;   // overlay: 4*32*51 floats < SIN
#pragma unroll
    for (int co = 0; co < 4; ++co) {
        float* p = s_out + co * (32 * SOP) + lane * SOP + t0;
        float2 a = upk(acc[co][0]);
        float2 b = upk(acc[co][1]);
        p[0] = a.x;
        p[1] = a.y;
        if (t0 + 2 < TT) p[2] = b.x;
        if (t0 + 3 < TT) p[3] = b.y;
    }
    __syncthreads();

    // fused spike-dynamics epilogue: 128 pixels (4co x 32w)
    if (tid < 128) {
        const int co = tid >> 5;
        const int w  = tid & 31;
        float* row = s_out + co * (32 * SOP) + w * SOP;
        float sd1 = 0.f, sd2 = 0.f, sp1 = 0.f, sp2 = 0.f;
#pragma unroll
        for (int t = 0; t < TT; ++t) {
            float m = fmaf(cR, sd2, row[t]);
            float s = (m >= theta) ? 1.f : 0.f;
            sd1 = fmaf(rR, sd1, s);
            sd2 = fmaf(rR, sd2, rR * sd1);
            if (EPI == 0) {
                row[t] = cP * sp2;
                sp1 = fmaf(rP, sp1, s);
                sp2 = fmaf(rP, sp2, rP * sp1);
            } else {
                row[t] = s;
            }
        }
    }
    __syncthreads();

    // structured coalesced store: warp-per-w-row, no division
#pragma unroll
    for (int co = 0; co < 4; ++co) {
        const float* sbase = s_out + co * (32 * SOP);
        float* gbase = out + (((long)(n * CHN + co) * HHT + h) * WWD + w0) * TT;
        for (int w = wrp; w < 32; w += 13) {
            const float* srow = sbase + w * SOP;
            float* grow = gbase + w * TT;
            grow[lane] = srow[lane];
            if (lane < TT - 32) grow[32 + lane] = srow[32 + lane];
        }
    }
}

// ---------------------------------------------------------------------------

extern "C" void kernel_launch(void* const* d_in, const int* in_sizes, int n_in,
                              void* d_out, int out_size) {
    const float* x  = (const float*)d_in[0];
    const float* w1 = (const float*)d_in[1];
    const float* w2 = (const float*)d_in[2];
    float* outp = (float*)d_out;

    float *bufA, *bufB;
    cudaGetSymbolAddress((void**)&bufA, g_bufA);
    cudaGetSymbolAddress((void**)&bufB, g_bufB);
    float4* wpack;
    cudaGetSymbolAddress((void**)&wpack, g_wpack);

    const int SMEM5 = 1 * 5 * 36 * TP * 4;   // 37440 B -> 3 blocks/SM
    const int SMEM3 = 2 * 3 * 34 * TP * 4;   // 42432 B -> 3 blocks/SM
    cudaFuncSetAttribute((const void*)conv_fused_kernel<5, 1, 0>,
                         cudaFuncAttributeMaxDynamicSharedMemorySize, SMEM5);
    cudaFuncSetAttribute((const void*)conv_fused_kernel<3, 2, 1>,
                         cudaFuncAttributeMaxDynamicSharedMemorySize, SMEM3);
    cudaFuncSetAttribute((const void*)psp_kernel,
                         cudaFuncAttributeMaxDynamicSharedMemorySize, PW_SMEM);

    const float r1  = (float)0.36787944117144233;   // exp(-1/tau1)
    const float cP1 = (float)2.718281828459045;     // e/tau1
    const float rR1 = (float)0.36787944117144233;   // exp(-1/tauRef1)
    const float cR1 = (float)(-54.365636569180902); // -scaleRef*theta1*e/tauRef1
    const float th1 = 20.0f;
    const float r2  = (float)0.6065306597126334;    // exp(-1/tau2)
    const float cP2 = (float)1.3591409142295225;    // e/tau2
    const float rR2 = (float)0.6065306597126334;    // exp(-1/tauRef2)
    const float cR2 = (float)(-54.365636569180902); // -scaleRef*theta2*e/tauRef2
    const float th2 = 40.0f;

    const int PGRID = NPIX / (PW_WARPS * 32);   // 2048
    dim3 cgrid(WWD / 32, HHT, NBATCH);          // (4,128,8)

    repack_kernel<<<1, 256>>>(w1, w2);
    cudaMemcpyToSymbolAsync(c_w5, wpack, 100 * sizeof(float4), 0,
                            cudaMemcpyDeviceToDevice, 0);
    cudaMemcpyToSymbolAsync(c_w3, wpack + 100, 36 * sizeof(float4), 0,
                            cudaMemcpyDeviceToDevice, 0);

    psp_kernel<<<PGRID, 256, PW_SMEM>>>(x, bufA, r1, cP1);
    conv_fused_kernel<5, 1, 0><<<cgrid, 416, SMEM5>>>(bufA, bufB,
                                                      rR1, cR1, th1, r2, cP2);
    conv_fused_kernel<3, 2, 1><<<cgrid, 416, SMEM3>>>(bufB, outp,
                                                      rR2, cR2, th2, 0.f, 0.f);
}